// round 5
// baseline (speedup 1.0000x reference)
#include <cuda_runtime.h>
#include <cstdint>

#define ROWS            128
#define ROW_N           262144          // 256*32*32
#define BLOCKS_PER_ROW  16
#define SEG_N           (ROW_N / BLOCKS_PER_ROW)   // 16384 elements per block
#define THREADS         256
#define WARPS           (THREADS / 32)             // 8
#define VEC_TOTAL       (SEG_N / 4 / THREADS)      // 16 float4 per thread
#define CHUNK           8                          // float4 buffered per iter
#define TOPK            5
#define CAND_PER_SEG    (WARPS * TOPK)             // 40
#define CAND_PER_ROW    (BLOCKS_PER_ROW * CAND_PER_SEG)  // 640

#define FULLMASK 0xFFFFFFFFu

// Scratch (no cudaMalloc allowed): per-(row,seg,warp) top-5 candidates.
__device__ float g_cand_val[ROWS * CAND_PER_ROW];
__device__ int   g_cand_idx[ROWS * CAND_PER_ROW];

// jax.lax.top_k stability: larger value wins; equal value -> smaller index wins.
__device__ __forceinline__ bool better(float v, int i, float bv, int bi) {
    return (v > bv) || (v == bv && i < bi);
}

// Insert (val, idx) into sorted-descending 5-entry register list.
__device__ __forceinline__ void ins5(float val, int idx, float v[TOPK], int id[TOPK]) {
    if (!better(val, idx, v[TOPK - 1], id[TOPK - 1])) return;   // common fast path
    v[TOPK - 1] = val; id[TOPK - 1] = idx;
    #pragma unroll
    for (int j = TOPK - 1; j > 0; --j) {
        if (better(v[j], id[j], v[j - 1], id[j - 1])) {
            float tv = v[j]; v[j] = v[j - 1]; v[j - 1] = tv;
            int   ti = id[j]; id[j] = id[j - 1]; id[j - 1] = ti;
        } else break;
    }
}

// Warp merge of 32 sorted 5-lists -> warp top-5, no barriers.
// For round r, the winning lane calls emit(r, bv, bi).
template <typename EMIT>
__device__ __forceinline__ void warp_top5(float v[TOPK], int id[TOPK], EMIT emit) {
    int p = 0;
    #pragma unroll
    for (int r = 0; r < TOPK; ++r) {
        const float mv = (p < TOPK) ? v[p]  : -INFINITY;
        const int   mi = (p < TOPK) ? id[p] : 0x7fffffff;
        float cv = mv; int ci = mi;
        #pragma unroll
        for (int off = 16; off > 0; off >>= 1) {
            const float ov = __shfl_down_sync(FULLMASK, cv, off);
            const int   oi = __shfl_down_sync(FULLMASK, ci, off);
            if (better(ov, oi, cv, ci)) { cv = ov; ci = oi; }
        }
        const float bv = __shfl_sync(FULLMASK, cv, 0);
        const int   bi = __shfl_sync(FULLMASK, ci, 0);
        if (mv == bv && mi == bi) {          // unique winner (indices distinct)
            ++p;
            emit(r, bv, bi);
        }
    }
}

// ---------------------------------------------------------------------------
// Stage 1: fused (stream-read x) + (stream-zero out) + (warp top-5 -> scratch)
// grid = ROWS * BLOCKS_PER_ROW = 2048, block = 256.  ZERO __syncthreads.
// ---------------------------------------------------------------------------
__global__ __launch_bounds__(THREADS)
void wta_stage1(const float* __restrict__ x, float* __restrict__ out) {
    const int b    = blockIdx.x;
    const int row  = b / BLOCKS_PER_ROW;
    const int seg  = b % BLOCKS_PER_ROW;
    const int t    = threadIdx.x;
    const int warp = t >> 5;

    const size_t base = (size_t)row * ROW_N + (size_t)seg * SEG_N;
    const float4* __restrict__ xv = (const float4*)(x + base);
    float4* __restrict__       ov = (float4*)(out + base);

    float v[TOPK]; int id[TOPK];
    #pragma unroll
    for (int j = 0; j < TOPK; ++j) { v[j] = -INFINITY; id[j] = 0x7fffffff; }

    const float4 z = make_float4(0.f, 0.f, 0.f, 0.f);

    #pragma unroll
    for (int c = 0; c < VEC_TOTAL / CHUNK; ++c) {
        float4 d[CHUNK];
        #pragma unroll
        for (int k = 0; k < CHUNK; ++k)
            d[k] = __ldcs(&xv[(c * CHUNK + k) * THREADS + t]);
        #pragma unroll
        for (int k = 0; k < CHUNK; ++k)
            __stcs(&ov[(c * CHUNK + k) * THREADS + t], z);
        #pragma unroll
        for (int k = 0; k < CHUNK; ++k) {
            const int gi = seg * SEG_N + ((c * CHUNK + k) * THREADS + t) * 4;
            ins5(d[k].x, gi + 0, v, id);
            ins5(d[k].y, gi + 1, v, id);
            ins5(d[k].z, gi + 2, v, id);
            ins5(d[k].w, gi + 3, v, id);
        }
    }

    const int wbase = ((row * BLOCKS_PER_ROW + seg) * WARPS + warp) * TOPK;
    warp_top5(v, id, [&](int r, float bv, int bi) {
        g_cand_val[wbase + r] = bv;
        g_cand_idx[wbase + r] = bi;
    });
}

// ---------------------------------------------------------------------------
// Stage 2: per-row reduce 640 candidates -> exact top-5; scatter 1.0f.
// grid = ROWS, block = 256.  Two __syncthreads total.
// ---------------------------------------------------------------------------
__global__ __launch_bounds__(THREADS)
void wta_stage2(float* __restrict__ out) {
    const int row  = blockIdx.x;
    const int t    = threadIdx.x;
    const int warp = t >> 5;
    const int lane = t & 31;

    __shared__ float wv[WARPS * TOPK];
    __shared__ int   wi[WARPS * TOPK];

    // Thread-local top-5 over strided candidates (640 / 256 = 2.5 each).
    float v[TOPK]; int id[TOPK];
    #pragma unroll
    for (int j = 0; j < TOPK; ++j) { v[j] = -INFINITY; id[j] = 0x7fffffff; }

    const int cbase = row * CAND_PER_ROW;
    for (int e = t; e < CAND_PER_ROW; e += THREADS)
        ins5(g_cand_val[cbase + e], g_cand_idx[cbase + e], v, id);

    // Warp merge -> 8x5 candidates in smem.
    warp_top5(v, id, [&](int r, float bv, int bi) {
        wv[warp * TOPK + r] = bv;
        wi[warp * TOPK + r] = bi;
    });
    __syncthreads();

    // Warp 0 merges the 40 survivors and scatters directly.
    if (warp == 0) {
        float fv[TOPK]; int fi[TOPK];
        #pragma unroll
        for (int j = 0; j < TOPK; ++j) { fv[j] = -INFINITY; fi[j] = 0x7fffffff; }
        if (lane < WARPS * TOPK)
            ins5(wv[lane], wi[lane], fv, fi);
        if (lane + 32 < WARPS * TOPK)
            ins5(wv[lane + 32], wi[lane + 32], fv, fi);

        warp_top5(fv, fi, [&](int r, float bv, int bi) {
            out[(size_t)row * ROW_N + bi] = 1.0f;
        });
    }
}

// ---------------------------------------------------------------------------
extern "C" void kernel_launch(void* const* d_in, const int* in_sizes, int n_in,
                              void* d_out, int out_size) {
    const float* x = (const float*)d_in[0];
    float* out = (float*)d_out;
    wta_stage1<<<ROWS * BLOCKS_PER_ROW, THREADS>>>(x, out);
    wta_stage2<<<ROWS, THREADS>>>(out);
}

// round 7
// speedup vs baseline: 3.5535x; 3.5535x over previous
#include <cuda_runtime.h>
#include <cstdint>

#define ROWS            128
#define ROW_N           262144          // 256*32*32
#define BLOCKS_PER_ROW  64
#define SEG_N           (ROW_N / BLOCKS_PER_ROW)   // 4096 elements per block
#define THREADS         256
#define WARPS           (THREADS / 32)             // 8
#define VEC             (SEG_N / 4 / THREADS)      // 4 float4 per thread
#define TOPK            5
#define CAND_PER_ROW    (BLOCKS_PER_ROW * WARPS * TOPK)   // 2560

#define FULLMASK 0xFFFFFFFFu

// Scratch (no cudaMalloc allowed): per-(row,seg,warp) top-5 candidates.
__device__ float g_cand_val[ROWS * CAND_PER_ROW];
__device__ int   g_cand_idx[ROWS * CAND_PER_ROW];

// jax.lax.top_k stability: larger value wins; equal value -> smaller index wins.
__device__ __forceinline__ bool better(float v, int i, float bv, int bi) {
    return (v > bv) || (v == bv && i < bi);
}

// BRANCHLESS sorted insert (descending). Exact tie semantics when elements are
// inserted in increasing-index order: strict '>' means an equal value never
// displaces an earlier-index entry. 5 FSETP + 9 FSEL + 9 SEL, no branches.
__device__ __forceinline__ void bins5(float val, int idx, float v[TOPK], int id[TOPK]) {
    const bool p0 = val > v[0];
    const bool p1 = val > v[1];
    const bool p2 = val > v[2];
    const bool p3 = val > v[3];
    const bool p4 = val > v[4];
    v[4]  = p4 ? (p3 ? v[3]  : val) : v[4];
    id[4] = p4 ? (p3 ? id[3] : idx) : id[4];
    v[3]  = p3 ? (p2 ? v[2]  : val) : v[3];
    id[3] = p3 ? (p2 ? id[2] : idx) : id[3];
    v[2]  = p2 ? (p1 ? v[1]  : val) : v[2];
    id[2] = p2 ? (p1 ? id[1] : idx) : id[2];
    v[1]  = p1 ? (p0 ? v[0]  : val) : v[1];
    id[1] = p1 ? (p0 ? id[0] : idx) : id[1];
    v[0]  = p0 ? val  : v[0];
    id[0] = p0 ? idx  : id[0];
}

// Index-aware branchless insert (for stage2 where arrival order is not monotone).
__device__ __forceinline__ void bins5_tie(float val, int idx, float v[TOPK], int id[TOPK]) {
    bool p[TOPK];
    #pragma unroll
    for (int j = 0; j < TOPK; ++j)
        p[j] = better(val, idx, v[j], id[j]);
    v[4]  = p[4] ? (p[3] ? v[3]  : val) : v[4];
    id[4] = p[4] ? (p[3] ? id[3] : idx) : id[4];
    v[3]  = p[3] ? (p[2] ? v[2]  : val) : v[3];
    id[3] = p[3] ? (p[2] ? id[2] : idx) : id[3];
    v[2]  = p[2] ? (p[1] ? v[1]  : val) : v[2];
    id[2] = p[2] ? (p[1] ? id[1] : idx) : id[2];
    v[1]  = p[1] ? (p[0] ? v[0]  : val) : v[1];
    id[1] = p[1] ? (p[0] ? id[0] : idx) : id[1];
    v[0]  = p[0] ? val  : v[0];
    id[0] = p[0] ? idx  : id[0];
}

// Warp merge of 32 sorted 5-lists -> warp top-5, no barriers, index-aware.
// For round r, the winning lane calls emit(r, bv, bi).
template <typename EMIT>
__device__ __forceinline__ void warp_top5(float v[TOPK], int id[TOPK], EMIT emit) {
    int p = 0;
    #pragma unroll
    for (int r = 0; r < TOPK; ++r) {
        const float mv = (p < TOPK) ? v[p]  : -INFINITY;
        const int   mi = (p < TOPK) ? id[p] : 0x7fffffff;
        float cv = mv; int ci = mi;
        #pragma unroll
        for (int off = 16; off > 0; off >>= 1) {
            const float ov = __shfl_down_sync(FULLMASK, cv, off);
            const int   oi = __shfl_down_sync(FULLMASK, ci, off);
            if (better(ov, oi, cv, ci)) { cv = ov; ci = oi; }
        }
        const float bv = __shfl_sync(FULLMASK, cv, 0);
        const int   bi = __shfl_sync(FULLMASK, ci, 0);
        if (mv == bv && mi == bi) {          // unique winner (indices distinct)
            ++p;
            emit(r, bv, bi);
        }
    }
}

// ---------------------------------------------------------------------------
// Stage 1: fused (stream-read x) + (stream-zero out) + branchless top-5.
// grid = 8192, block = 256. ZERO branches in the hot loop, zero __syncthreads.
// ---------------------------------------------------------------------------
__global__ __launch_bounds__(THREADS)
void wta_stage1(const float* __restrict__ x, float* __restrict__ out) {
    const int b    = blockIdx.x;
    const int row  = b >> 6;            // / BLOCKS_PER_ROW
    const int seg  = b & 63;            // % BLOCKS_PER_ROW
    const int t    = threadIdx.x;
    const int warp = t >> 5;

    const size_t base = (size_t)row * ROW_N + (size_t)seg * SEG_N;
    const float4* __restrict__ xv = (const float4*)(x + base);
    float4* __restrict__       ov = (float4*)(out + base);

    float v[TOPK]; int id[TOPK];
    #pragma unroll
    for (int j = 0; j < TOPK; ++j) { v[j] = -INFINITY; id[j] = 0x7fffffff; }

    // Front-batched streaming loads (MLP=4), then streaming zero-stores.
    float4 d[VEC];
    #pragma unroll
    for (int k = 0; k < VEC; ++k)
        d[k] = __ldcs(&xv[k * THREADS + t]);

    const float4 z = make_float4(0.f, 0.f, 0.f, 0.f);
    #pragma unroll
    for (int k = 0; k < VEC; ++k)
        __stcs(&ov[k * THREADS + t], z);

    // Branchless per-element insert; indices strictly increasing per thread.
    const int tbase = seg * SEG_N + t * 4;
    #pragma unroll
    for (int k = 0; k < VEC; ++k) {
        const int gi = tbase + k * (THREADS * 4);   // + compile-time const lanes
        bins5(d[k].x, gi + 0, v, id);
        bins5(d[k].y, gi + 1, v, id);
        bins5(d[k].z, gi + 2, v, id);
        bins5(d[k].w, gi + 3, v, id);
    }

    // Warp shfl merge -> 5 candidates per warp, written straight to scratch.
    const int wbase = ((row * BLOCKS_PER_ROW + seg) * WARPS + warp) * TOPK;
    warp_top5(v, id, [&](int r, float bv, int bi) {
        g_cand_val[wbase + r] = bv;
        g_cand_idx[wbase + r] = bi;
    });
}

// ---------------------------------------------------------------------------
// Stage 2: per-row reduce 2560 candidates -> exact top-5; scatter 1.0f.
// grid = ROWS, block = 256. One __syncthreads.
// ---------------------------------------------------------------------------
__global__ __launch_bounds__(THREADS)
void wta_stage2(float* __restrict__ out) {
    const int row  = blockIdx.x;
    const int t    = threadIdx.x;
    const int warp = t >> 5;
    const int lane = t & 31;

    __shared__ float wv[WARPS * TOPK];
    __shared__ int   wi[WARPS * TOPK];

    float v[TOPK]; int id[TOPK];
    #pragma unroll
    for (int j = 0; j < TOPK; ++j) { v[j] = -INFINITY; id[j] = 0x7fffffff; }

    const int cbase = row * CAND_PER_ROW;
    #pragma unroll 2
    for (int e = t; e < CAND_PER_ROW; e += THREADS)
        bins5_tie(g_cand_val[cbase + e], g_cand_idx[cbase + e], v, id);

    // Warp merge -> 8x5 candidates in smem.
    warp_top5(v, id, [&](int r, float bv, int bi) {
        wv[warp * TOPK + r] = bv;
        wi[warp * TOPK + r] = bi;
    });
    __syncthreads();

    // Warp 0 merges the 40 survivors and scatters 1.0 directly.
    if (warp == 0) {
        float fv[TOPK]; int fi[TOPK];
        #pragma unroll
        for (int j = 0; j < TOPK; ++j) { fv[j] = -INFINITY; fi[j] = 0x7fffffff; }
        if (lane < WARPS * TOPK)
            bins5_tie(wv[lane], wi[lane], fv, fi);
        if (lane + 32 < WARPS * TOPK)
            bins5_tie(wv[lane + 32], wi[lane + 32], fv, fi);

        warp_top5(fv, fi, [&](int r, float bv, int bi) {
            out[(size_t)row * ROW_N + bi] = 1.0f;
        });
    }
}

// ---------------------------------------------------------------------------
extern "C" void kernel_launch(void* const* d_in, const int* in_sizes, int n_in,
                              void* d_out, int out_size) {
    const float* x = (const float*)d_in[0];
    float* out = (float*)d_out;
    wta_stage1<<<ROWS * BLOCKS_PER_ROW, THREADS>>>(x, out);
    wta_stage2<<<ROWS, THREADS>>>(out);
}

// round 8
// speedup vs baseline: 6.3306x; 1.7815x over previous
#include <cuda_runtime.h>
#include <cstdint>

#define ROWS            128
#define ROW_N           262144                     // 256*32*32
#define BLOCKS_PER_ROW  32
#define SEG_N           (ROW_N / BLOCKS_PER_ROW)   // 8192 elements per block
#define THREADS         256
#define WARPS           (THREADS / 32)             // 8
#define VEC             (SEG_N / 4 / THREADS)      // 8 float4 per thread
#define CHUNK           4                          // float4 buffered per pass
#define TOPK            5
#define CAND_PER_ROW    (BLOCKS_PER_ROW * WARPS * TOPK)   // 1280

#define FULLMASK 0xFFFFFFFFu

// Scratch (no cudaMalloc allowed). Zero-initialized device globals.
__device__ float g_cand_val[ROWS * CAND_PER_ROW];
__device__ int   g_cand_idx[ROWS * CAND_PER_ROW];
__device__ int   g_row_cnt[ROWS];                  // last-block-closes-row counters

// jax.lax.top_k stability: larger value wins; equal value -> smaller index wins.
__device__ __forceinline__ bool better(float v, int i, float bv, int bi) {
    return (v > bv) || (v == bv && i < bi);
}

// Register-resident 5-way select (avoids local-memory spill from dynamic index).
__device__ __forceinline__ float get5f(const float v[TOPK], int p) {
    float r = (p == 0) ? v[0] : v[1];
    r = (p == 2) ? v[2] : r;
    r = (p == 3) ? v[3] : r;
    r = (p == 4) ? v[4] : r;
    return (p >= TOPK) ? -INFINITY : r;
}
__device__ __forceinline__ int get5i(const int v[TOPK], int p) {
    int r = (p == 0) ? v[0] : v[1];
    r = (p == 2) ? v[2] : r;
    r = (p == 3) ? v[3] : r;
    r = (p == 4) ? v[4] : r;
    return (p >= TOPK) ? 0x7fffffff : r;
}

// BRANCHLESS sorted insert (descending). Exact ties when inserted in
// increasing-index order (strict '>' keeps the earlier index).
__device__ __forceinline__ void bins5(float val, int idx, float v[TOPK], int id[TOPK]) {
    const bool p0 = val > v[0];
    const bool p1 = val > v[1];
    const bool p2 = val > v[2];
    const bool p3 = val > v[3];
    const bool p4 = val > v[4];
    v[4]  = p4 ? (p3 ? v[3]  : val) : v[4];
    id[4] = p4 ? (p3 ? id[3] : idx) : id[4];
    v[3]  = p3 ? (p2 ? v[2]  : val) : v[3];
    id[3] = p3 ? (p2 ? id[2] : idx) : id[3];
    v[2]  = p2 ? (p1 ? v[1]  : val) : v[2];
    id[2] = p2 ? (p1 ? id[1] : idx) : id[2];
    v[1]  = p1 ? (p0 ? v[0]  : val) : v[1];
    id[1] = p1 ? (p0 ? id[0] : idx) : id[1];
    v[0]  = p0 ? val  : v[0];
    id[0] = p0 ? idx  : id[0];
}

// Index-aware branchless insert (arrival order not monotone).
__device__ __forceinline__ void bins5_tie(float val, int idx, float v[TOPK], int id[TOPK]) {
    bool p[TOPK];
    #pragma unroll
    for (int j = 0; j < TOPK; ++j)
        p[j] = better(val, idx, v[j], id[j]);
    v[4]  = p[4] ? (p[3] ? v[3]  : val) : v[4];
    id[4] = p[4] ? (p[3] ? id[3] : idx) : id[4];
    v[3]  = p[3] ? (p[2] ? v[2]  : val) : v[3];
    id[3] = p[3] ? (p[2] ? id[2] : idx) : id[3];
    v[2]  = p[2] ? (p[1] ? v[1]  : val) : v[2];
    id[2] = p[2] ? (p[1] ? id[1] : idx) : id[2];
    v[1]  = p[1] ? (p[0] ? v[0]  : val) : v[1];
    id[1] = p[1] ? (p[0] ? id[0] : idx) : id[1];
    v[0]  = p[0] ? val  : v[0];
    id[0] = p[0] ? idx  : id[0];
}

// Warp argmax with index tie-break; returns winner broadcast to all lanes.
__device__ __forceinline__ void warp_argmax(float& cv, int& ci) {
    #pragma unroll
    for (int off = 16; off > 0; off >>= 1) {
        const float ov = __shfl_down_sync(FULLMASK, cv, off);
        const int   oi = __shfl_down_sync(FULLMASK, ci, off);
        if (better(ov, oi, cv, ci)) { cv = ov; ci = oi; }
    }
    cv = __shfl_sync(FULLMASK, cv, 0);
    ci = __shfl_sync(FULLMASK, ci, 0);
}

// Warp merge of 32 lanes each holding TWO sorted 5-lists -> warp top-5.
// Winning lane (globally unique index) calls emit(r, bv, bi).
template <typename EMIT>
__device__ __forceinline__ void warp_top5_dual(
    const float va[TOPK], const int ia[TOPK],
    const float vb[TOPK], const int ib[TOPK], EMIT emit) {
    int pa = 0, pb = 0;
    #pragma unroll
    for (int r = 0; r < TOPK; ++r) {
        const float av = get5f(va, pa); const int ai = get5i(ia, pa);
        const float bv2 = get5f(vb, pb); const int bi2 = get5i(ib, pb);
        const bool useA = better(av, ai, bv2, bi2);
        const float mv = useA ? av : bv2;
        const int   mi = useA ? ai : bi2;
        float cv = mv; int ci = mi;
        warp_argmax(cv, ci);
        if (mv == cv && mi == ci) {       // unique: all indices distinct
            if (useA) ++pa; else ++pb;
            emit(r, cv, ci);
        }
    }
}

// Warp merge of 32 single sorted 5-lists -> warp top-5.
template <typename EMIT>
__device__ __forceinline__ void warp_top5(const float v[TOPK], const int id[TOPK], EMIT emit) {
    int p = 0;
    #pragma unroll
    for (int r = 0; r < TOPK; ++r) {
        const float mv = get5f(v, p); const int mi = get5i(id, p);
        float cv = mv; int ci = mi;
        warp_argmax(cv, ci);
        if (mv == cv && mi == ci) {
            ++p;
            emit(r, cv, ci);
        }
    }
}

// ---------------------------------------------------------------------------
// Fused kernel: stream-read x + stream-zero out + dual-list branchless top-5
// + warp shfl merge -> scratch; last block of each row closes the row
// (reduces 1280 candidates, scatters 1.0). grid = 4096, block = 256.
// ---------------------------------------------------------------------------
__global__ __launch_bounds__(THREADS)
void wta_fused(const float* __restrict__ x, float* __restrict__ out) {
    const int b    = blockIdx.x;
    const int row  = b >> 5;            // / BLOCKS_PER_ROW
    const int seg  = b & 31;            // % BLOCKS_PER_ROW
    const int t    = threadIdx.x;
    const int warp = t >> 5;
    const int lane = t & 31;

    const size_t base = (size_t)row * ROW_N + (size_t)seg * SEG_N;
    const float4* __restrict__ xv = (const float4*)(x + base);
    float4* __restrict__       ov = (float4*)(out + base);

    // Two independent lists -> 2x ILP on the serial insert chain.
    float va[TOPK], vb[TOPK]; int ia[TOPK], ib[TOPK];
    #pragma unroll
    for (int j = 0; j < TOPK; ++j) {
        va[j] = -INFINITY; ia[j] = 0x7fffffff;
        vb[j] = -INFINITY; ib[j] = 0x7fffffff;
    }

    const float4 z = make_float4(0.f, 0.f, 0.f, 0.f);
    const int tbase = seg * SEG_N + t * 4;

    #pragma unroll
    for (int c = 0; c < VEC / CHUNK; ++c) {
        float4 d[CHUNK];
        #pragma unroll
        for (int k = 0; k < CHUNK; ++k)
            d[k] = __ldcs(&xv[(c * CHUNK + k) * THREADS + t]);
        #pragma unroll
        for (int k = 0; k < CHUNK; ++k)
            __stcs(&ov[(c * CHUNK + k) * THREADS + t], z);
        #pragma unroll
        for (int k = 0; k < CHUNK; ++k) {
            const int gi = tbase + (c * CHUNK + k) * (THREADS * 4);
            if (k & 1) {     // odd float4 -> list B (indices increasing per list)
                bins5(d[k].x, gi + 0, vb, ib);
                bins5(d[k].y, gi + 1, vb, ib);
                bins5(d[k].z, gi + 2, vb, ib);
                bins5(d[k].w, gi + 3, vb, ib);
            } else {         // even float4 -> list A
                bins5(d[k].x, gi + 0, va, ia);
                bins5(d[k].y, gi + 1, va, ia);
                bins5(d[k].z, gi + 2, va, ia);
                bins5(d[k].w, gi + 3, va, ia);
            }
        }
    }

    // Warp merge (2-head pop) -> 5 candidates/warp straight to scratch.
    const int wbase = ((row * BLOCKS_PER_ROW + seg) * WARPS + warp) * TOPK;
    warp_top5_dual(va, ia, vb, ib, [&](int r, float bv, int bi) {
        g_cand_val[wbase + r] = bv;
        g_cand_idx[wbase + r] = bi;
    });

    // ---- last block of this row closes it -------------------------------
    __threadfence();                       // candidate stores -> device scope
    __shared__ int s_last;
    __syncthreads();
    if (t == 0) {
        const int old = atomicAdd(&g_row_cnt[row], 1);
        s_last = (old == BLOCKS_PER_ROW - 1);
    }
    __syncthreads();
    if (!s_last) return;
    if (t == 0) g_row_cnt[row] = 0;        // self-reset: graph-replay safe

    // Reduce this row's 1280 candidates -> exact top-5; scatter 1.0.
    float v[TOPK]; int id[TOPK];
    #pragma unroll
    for (int j = 0; j < TOPK; ++j) { v[j] = -INFINITY; id[j] = 0x7fffffff; }

    const int cbase = row * CAND_PER_ROW;
    #pragma unroll
    for (int e = t; e < CAND_PER_ROW; e += THREADS)
        bins5_tie(__ldcg(&g_cand_val[cbase + e]),     // bypass L1: other SMs wrote
                  __ldcg(&g_cand_idx[cbase + e]), v, id);

    __shared__ float wv[WARPS * TOPK];
    __shared__ int   wi[WARPS * TOPK];
    warp_top5(v, id, [&](int r, float bv, int bi) {
        wv[warp * TOPK + r] = bv;
        wi[warp * TOPK + r] = bi;
    });
    __syncthreads();

    if (warp == 0) {
        float fv[TOPK]; int fi[TOPK];
        #pragma unroll
        for (int j = 0; j < TOPK; ++j) { fv[j] = -INFINITY; fi[j] = 0x7fffffff; }
        if (lane < WARPS * TOPK)
            bins5_tie(wv[lane], wi[lane], fv, fi);
        if (lane + 32 < WARPS * TOPK)
            bins5_tie(wv[lane + 32], wi[lane + 32], fv, fi);

        warp_top5(fv, fi, [&](int r, float bv, int bi) {
            out[(size_t)row * ROW_N + bi] = 1.0f;
        });
    }
}

// ---------------------------------------------------------------------------
extern "C" void kernel_launch(void* const* d_in, const int* in_sizes, int n_in,
                              void* d_out, int out_size) {
    const float* x = (const float*)d_in[0];
    float* out = (float*)d_out;
    wta_fused<<<ROWS * BLOCKS_PER_ROW, THREADS>>>(x, out);
}

// round 9
// speedup vs baseline: 7.5514x; 1.1929x over previous
#include <cuda_runtime.h>
#include <cstdint>

#define ROWS            128
#define ROW_N           262144                     // 256*32*32
#define BLOCKS_PER_ROW  32
#define SEG_N           (ROW_N / BLOCKS_PER_ROW)   // 8192 elements per block
#define THREADS         256
#define WARPS           (THREADS / 32)             // 8
#define VEC             (SEG_N / 4 / THREADS)      // 8 float4 (= groups) per thread
#define CHUNK           4                          // float4 buffered per pass
#define TOPK            5
#define CAND_PER_ROW    (BLOCKS_PER_ROW * WARPS * TOPK)   // 1280 group candidates

#define FULLMASK 0xFFFFFFFFu

// Scratch (no cudaMalloc allowed). Zero-initialized device globals.
__device__ float g_cand_val[ROWS * CAND_PER_ROW];   // group max
__device__ int   g_cand_idx[ROWS * CAND_PER_ROW];   // group base index (row-relative)
__device__ int   g_row_cnt[ROWS];                   // last-block-closes-row counters

// larger value wins; equal value -> smaller index wins (jax.lax.top_k stability).
__device__ __forceinline__ bool better(float v, int i, float bv, int bi) {
    return (v > bv) || (v == bv && i < bi);
}

// Register-resident 5-way select (avoids local-memory spill from dynamic index).
__device__ __forceinline__ float get5f(const float v[TOPK], int p) {
    float r = (p == 0) ? v[0] : v[1];
    r = (p == 2) ? v[2] : r;
    r = (p == 3) ? v[3] : r;
    r = (p == 4) ? v[4] : r;
    return (p >= TOPK) ? -INFINITY : r;
}
__device__ __forceinline__ int get5i(const int v[TOPK], int p) {
    int r = (p == 0) ? v[0] : v[1];
    r = (p == 2) ? v[2] : r;
    r = (p == 3) ? v[3] : r;
    r = (p == 4) ? v[4] : r;
    return (p >= TOPK) ? 0x7fffffff : r;
}

// BRANCHLESS sorted insert (descending). Exact ties when inserted in
// increasing-index order (strict '>' keeps the earlier index).
__device__ __forceinline__ void bins5(float val, int idx, float v[TOPK], int id[TOPK]) {
    const bool p0 = val > v[0];
    const bool p1 = val > v[1];
    const bool p2 = val > v[2];
    const bool p3 = val > v[3];
    const bool p4 = val > v[4];
    v[4]  = p4 ? (p3 ? v[3]  : val) : v[4];
    id[4] = p4 ? (p3 ? id[3] : idx) : id[4];
    v[3]  = p3 ? (p2 ? v[2]  : val) : v[3];
    id[3] = p3 ? (p2 ? id[2] : idx) : id[3];
    v[2]  = p2 ? (p1 ? v[1]  : val) : v[2];
    id[2] = p2 ? (p1 ? id[1] : idx) : id[2];
    v[1]  = p1 ? (p0 ? v[0]  : val) : v[1];
    id[1] = p1 ? (p0 ? id[0] : idx) : id[1];
    v[0]  = p0 ? val  : v[0];
    id[0] = p0 ? idx  : id[0];
}

// Index-aware branchless insert (arrival order not monotone).
__device__ __forceinline__ void bins5_tie(float val, int idx, float v[TOPK], int id[TOPK]) {
    bool p[TOPK];
    #pragma unroll
    for (int j = 0; j < TOPK; ++j)
        p[j] = better(val, idx, v[j], id[j]);
    v[4]  = p[4] ? (p[3] ? v[3]  : val) : v[4];
    id[4] = p[4] ? (p[3] ? id[3] : idx) : id[4];
    v[3]  = p[3] ? (p[2] ? v[2]  : val) : v[3];
    id[3] = p[3] ? (p[2] ? id[2] : idx) : id[3];
    v[2]  = p[2] ? (p[1] ? v[1]  : val) : v[2];
    id[2] = p[2] ? (p[1] ? id[1] : idx) : id[2];
    v[1]  = p[1] ? (p[0] ? v[0]  : val) : v[1];
    id[1] = p[1] ? (p[0] ? id[0] : idx) : id[1];
    v[0]  = p[0] ? val  : v[0];
    id[0] = p[0] ? idx  : id[0];
}

// Warp argmax with index tie-break; winner broadcast to all lanes.
__device__ __forceinline__ void warp_argmax(float& cv, int& ci) {
    #pragma unroll
    for (int off = 16; off > 0; off >>= 1) {
        const float ov = __shfl_down_sync(FULLMASK, cv, off);
        const int   oi = __shfl_down_sync(FULLMASK, ci, off);
        if (better(ov, oi, cv, ci)) { cv = ov; ci = oi; }
    }
    cv = __shfl_sync(FULLMASK, cv, 0);
    ci = __shfl_sync(FULLMASK, ci, 0);
}

// Warp merge of 32 sorted 5-lists -> warp top-5. Winning lane calls emit.
template <typename EMIT>
__device__ __forceinline__ void warp_top5(const float v[TOPK], const int id[TOPK], EMIT emit) {
    int p = 0;
    #pragma unroll
    for (int r = 0; r < TOPK; ++r) {
        const float mv = get5f(v, p); const int mi = get5i(id, p);
        float cv = mv; int ci = mi;
        warp_argmax(cv, ci);
        if (mv == cv && mi == ci) {          // unique: all indices distinct
            ++p;
            emit(r, cv, ci);
        }
    }
}

// ---------------------------------------------------------------------------
// Fused kernel. Hot loop: stream-read x, stream-zero out, 3 FMNMX -> group max,
// one branchless insert per GROUP of 4. Candidates are (groupmax, groupbase).
// Last block of each row reduces 1280 group candidates -> top-5 groups,
// re-reads those 20 elements from x, exact top-5 of 20, scatters 1.0.
// grid = 4096, block = 256.
// ---------------------------------------------------------------------------
__global__ __launch_bounds__(THREADS)
void wta_fused(const float* __restrict__ x, float* __restrict__ out) {
    const int b    = blockIdx.x;
    const int row  = b >> 5;            // / BLOCKS_PER_ROW
    const int seg  = b & 31;            // % BLOCKS_PER_ROW
    const int t    = threadIdx.x;
    const int warp = t >> 5;
    const int lane = t & 31;

    const size_t base = (size_t)row * ROW_N + (size_t)seg * SEG_N;
    const float4* __restrict__ xv = (const float4*)(x + base);
    float4* __restrict__       ov = (float4*)(out + base);

    float v[TOPK]; int id[TOPK];
    #pragma unroll
    for (int j = 0; j < TOPK; ++j) { v[j] = -INFINITY; id[j] = 0x7fffffff; }

    const float4 z = make_float4(0.f, 0.f, 0.f, 0.f);
    const int tbase = seg * SEG_N + t * 4;

    #pragma unroll
    for (int c = 0; c < VEC / CHUNK; ++c) {
        float4 d[CHUNK];
        #pragma unroll
        for (int k = 0; k < CHUNK; ++k)
            d[k] = __ldcs(&xv[(c * CHUNK + k) * THREADS + t]);
        #pragma unroll
        for (int k = 0; k < CHUNK; ++k)
            __stcs(&ov[(c * CHUNK + k) * THREADS + t], z);
        #pragma unroll
        for (int k = 0; k < CHUNK; ++k) {
            // 3 FMNMX: group max (value only). Group base is loop-constant math.
            const float gm = fmaxf(fmaxf(d[k].x, d[k].y), fmaxf(d[k].z, d[k].w));
            const int gbase = tbase + (c * CHUNK + k) * (THREADS * 4);
            bins5(gm, gbase, v, id);         // one insert per 4 elements
        }
    }

    // Warp merge -> 5 group candidates per warp straight to scratch.
    const int wbase = ((row * BLOCKS_PER_ROW + seg) * WARPS + warp) * TOPK;
    warp_top5(v, id, [&](int r, float bv, int bi) {
        g_cand_val[wbase + r] = bv;
        g_cand_idx[wbase + r] = bi;
    });

    // ---- last block of this row closes it -------------------------------
    __threadfence();                       // candidate stores -> device scope
    __shared__ int s_last;
    __syncthreads();
    if (t == 0) {
        const int old = atomicAdd(&g_row_cnt[row], 1);
        s_last = (old == BLOCKS_PER_ROW - 1);
    }
    __syncthreads();
    if (!s_last) return;
    if (t == 0) g_row_cnt[row] = 0;        // self-reset: graph-replay safe

    // Reduce this row's 1280 group candidates -> top-5 GROUPS.
    float rv[TOPK]; int ri[TOPK];
    #pragma unroll
    for (int j = 0; j < TOPK; ++j) { rv[j] = -INFINITY; ri[j] = 0x7fffffff; }

    const int cbase = row * CAND_PER_ROW;
    #pragma unroll
    for (int e = t; e < CAND_PER_ROW; e += THREADS)
        bins5_tie(__ldcg(&g_cand_val[cbase + e]),     // bypass L1: other SMs wrote
                  __ldcg(&g_cand_idx[cbase + e]), rv, ri);

    __shared__ float wv[WARPS * TOPK];
    __shared__ int   wi[WARPS * TOPK];
    __shared__ int   s_win[TOPK];
    warp_top5(rv, ri, [&](int r, float bv, int bi) {
        wv[warp * TOPK + r] = bv;
        wi[warp * TOPK + r] = bi;
    });
    __syncthreads();

    if (warp == 0) {
        float fv[TOPK]; int fi[TOPK];
        #pragma unroll
        for (int j = 0; j < TOPK; ++j) { fv[j] = -INFINITY; fi[j] = 0x7fffffff; }
        if (lane < WARPS * TOPK)
            bins5_tie(wv[lane], wi[lane], fv, fi);
        if (lane + 32 < WARPS * TOPK)
            bins5_tie(wv[lane + 32], wi[lane + 32], fv, fi);

        // Top-5 groups' base indices -> s_win.
        warp_top5(fv, fi, [&](int r, float bv, int bi) {
            s_win[r] = bi;
        });
        __syncwarp();

        // Expand the 5 winning groups: 20 elements, exact (val, idx).
        const float* __restrict__ xr = x + (size_t)row * ROW_N;
        float ev = -INFINITY; int ei = 0x7fffffff;
        if (lane < 4 * TOPK) {
            ei = s_win[lane >> 2] + (lane & 3);
            ev = __ldcg(&xr[ei]);
        }
        // 5 rounds of warp argmax with exact tie rules; lane 0 scatters.
        #pragma unroll
        for (int r = 0; r < TOPK; ++r) {
            float cv = ev; int ci = ei;
            warp_argmax(cv, ci);
            if (ci == ei) ev = -INFINITY;          // remove winner (unique idx)
            if (lane == 0)
                out[(size_t)row * ROW_N + ci] = 1.0f;
        }
    }
}

// ---------------------------------------------------------------------------
extern "C" void kernel_launch(void* const* d_in, const int* in_sizes, int n_in,
                              void* d_out, int out_size) {
    const float* x = (const float*)d_in[0];
    float* out = (float*)d_out;
    wta_fused<<<ROWS * BLOCKS_PER_ROW, THREADS>>>(x, out);
}